// round 12
// baseline (speedup 1.0000x reference)
#include <cuda_runtime.h>

#define N_NODES 100000
#define N_EDGES 3200000
#define N_FEAT  512
#define HID     16
#define N_CLS   64
#define NB_N    391              // ceil(N_NODES/256)

#define XS_STRIDE 17                              // floats; odd => conflict-free LDS
#define G_SMEM_BYTES ((N_FEAT * HID + 256 * XS_STRIDE) * 4)   // 32768 + 17408 = 50176

// ---------------- scratch (device globals; statically zero-initialized) ----
__device__ float g_h1[N_NODES * HID];    // dinv-scaled x@W1
__device__ float g_h2[N_NODES * HID];    // dinv-scaled layer-1 output
__device__ float g_dinv[N_NODES];
__device__ int   g_cnt[N_NODES];         // in-degree histogram (re-zeroed by k_scan)
__device__ int   g_row[N_NODES + 1];     // CSR row offsets
__device__ int   g_cursor[N_NODES];
__device__ int   g_edge[N_EDGES];        // src only, dst-grouped
__device__ unsigned long long g_state[NB_N];  // lookback: status(hi32) | value(lo32)
__device__ int   g_is64;

// ---------------- hist: per-block dtype detect + degree histogram -----------
__global__ __launch_bounds__(256) void k_hist(const void* __restrict__ eidx, int E) {
    int gtid = blockIdx.x * blockDim.x + threadIdx.x;
    if (gtid < NB_N) g_state[gtid] = 0ull;

    unsigned w = 0;
    if (threadIdx.x < 32) {
        int ee = blockIdx.x * blockDim.x + threadIdx.x;
        if (ee < E) w = ((const unsigned*)eidx)[2 * ee + 1];
    }
    int any = __syncthreads_or((int)(w != 0));
    int is64 = (any == 0);
    if (blockIdx.x == 0 && threadIdx.x == 0) g_is64 = is64;

    if (gtid < E) {
        int d = is64 ? (int)((const long long*)eidx)[E + gtid]
                     : ((const int*)eidx)[E + gtid];
        atomicAdd(&g_cnt[d], 1);
    }
}

// ---------------- single-kernel scan (decoupled lookback) -------------------
__global__ __launch_bounds__(256) void k_scan() {
    int i    = blockIdx.x * blockDim.x + threadIdx.x;
    int lane = threadIdx.x & 31, warp = threadIdx.x >> 5;
    int v = (i < N_NODES) ? g_cnt[i] : 0;

    int x = v;
#pragma unroll
    for (int o = 1; o < 32; o <<= 1) {
        int y = __shfl_up_sync(0xffffffffu, x, o);
        if (lane >= o) x += y;
    }
    __shared__ int ws[8];
    __shared__ int s_pref;
    if (lane == 31) ws[warp] = x;
    __syncthreads();

    if (threadIdx.x == 0) {
        int s = 0;
#pragma unroll
        for (int k = 0; k < 8; k++) { int t = ws[k]; ws[k] = s; s += t; }
        int total = s;
        int prefix = 0;
        if (blockIdx.x == 0) {
            __threadfence();
            atomicExch(&g_state[0], (2ull << 32) | (unsigned)total);          // P
        } else {
            atomicExch(&g_state[blockIdx.x], (1ull << 32) | (unsigned)total); // A
            int p = blockIdx.x - 1;
            unsigned ns = 32;
            while (true) {
                unsigned long long st = *(volatile unsigned long long*)&g_state[p];
                unsigned stat = (unsigned)(st >> 32);
                if (stat == 0u) {
                    __nanosleep(ns);
                    if (ns < 1024u) ns <<= 1;
                    continue;
                }
                ns = 32;
                prefix += (int)(unsigned)(st & 0xffffffffu);
                if (stat == 2u) break;
                p--;
            }
            __threadfence();
            atomicExch(&g_state[blockIdx.x],
                       (2ull << 32) | (unsigned)(prefix + total));            // P
        }
        s_pref = prefix;
    }
    __syncthreads();

    int excl = s_pref + ws[warp] + x - v;
    if (i < N_NODES) {
        g_row[i]    = excl;
        g_cursor[i] = excl;
        g_dinv[i]   = rsqrtf((float)v + 1.0f);     // +1: self-loop
        g_cnt[i]    = 0;                            // ready for next replay
        if (i == N_NODES - 1) g_row[N_NODES] = excl + v;
    }
}

// ---------------- fill CSR: dst-grouped src index ---------------------------
__global__ __launch_bounds__(256) void k_fill(const void* __restrict__ eidx, int E) {
    int e = blockIdx.x * blockDim.x + threadIdx.x;
    if (e >= E) return;
    int s, d;
    if (g_is64) {
        const long long* p = (const long long*)eidx;
        s = (int)p[e]; d = (int)p[E + e];
    } else {
        const int* p = (const int*)eidx;
        s = p[e]; d = p[E + e];
    }
    int pos = atomicAdd(&g_cursor[d], 1);
    g_edge[pos] = s;
}

// ---------------- GEMM1 v3: thread-per-node, occupancy-first ----------------
// 256 nodes/block; x staged per 16-k chunk (coalesced LDG.128, stride-17 smem);
// W[k][0..15] broadcast via LDS.128; acc in 8 packed f32x2.
__global__ __launch_bounds__(256, 4) void k_gemm1(const float* __restrict__ x,
                                                  const float* __restrict__ W1) {
    extern __shared__ float sm[];
    float* Wsm = sm;                       // [512][16] verbatim
    float* xs  = sm + N_FEAT * HID;        // [256][17]

    for (int i = threadIdx.x; i < N_FEAT * HID; i += blockDim.x) Wsm[i] = W1[i];

    int nbase = blockIdx.x * 256;

    unsigned long long acc[8];
#pragma unroll
    for (int j = 0; j < 8; j++) acc[j] = 0ull;

    for (int chunk = 0; chunk < 32; chunk++) {
        int k0 = chunk * 16;
        __syncthreads();                   // prev compute done (chunk0: W ready)
        // stage 256 rows x 16 k = 1024 float4; 4 per thread, 4 thr/row coalesced
#pragma unroll
        for (int i = 0; i < 4; i++) {
            int id = threadIdx.x + i * 256;
            int r = id >> 2, c = id & 3;
            int rn = nbase + r;
            if (rn > N_NODES - 1) rn = N_NODES - 1;
            float4 t = __ldg((const float4*)(x + (size_t)rn * N_FEAT + k0) + c);
            int a = r * XS_STRIDE + c * 4;
            xs[a] = t.x; xs[a + 1] = t.y; xs[a + 2] = t.z; xs[a + 3] = t.w;
        }
        __syncthreads();

#pragma unroll
        for (int kk = 0; kk < 16; kk++) {
            float xv = xs[threadIdx.x * XS_STRIDE + kk];
            unsigned long long xx;
            asm("mov.b64 %0, {%1, %1};" : "=l"(xx) : "f"(xv));
            const float4* wr = (const float4*)(Wsm + (k0 + kk) * HID);
#pragma unroll
            for (int q = 0; q < 4; q++) {
                float4 w = wr[q];                  // LDS.128 broadcast
                unsigned long long w01, w23;
                asm("mov.b64 %0, {%1, %2};" : "=l"(w01) : "f"(w.x), "f"(w.y));
                asm("mov.b64 %0, {%1, %2};" : "=l"(w23) : "f"(w.z), "f"(w.w));
                asm("fma.rn.f32x2 %0, %1, %2, %0;" : "+l"(acc[2 * q])     : "l"(xx), "l"(w01));
                asm("fma.rn.f32x2 %0, %1, %2, %0;" : "+l"(acc[2 * q + 1]) : "l"(xx), "l"(w23));
            }
        }
    }

    int n = nbase + threadIdx.x;
    if (n < N_NODES) {
        float dn = g_dinv[n];
        float av[16];
#pragma unroll
        for (int j = 0; j < 8; j++)
            asm("mov.b64 {%0, %1}, %2;" : "=f"(av[2 * j]), "=f"(av[2 * j + 1]) : "l"(acc[j]));
        float4* o = (float4*)(g_h1 + (size_t)n * HID);
#pragma unroll
        for (int q = 0; q < 4; q++)
            o[q] = make_float4(av[4 * q] * dn, av[4 * q + 1] * dn,
                               av[4 * q + 2] * dn, av[4 * q + 3] * dn);
    }
}

// ---------------- agg layer 1: warp-per-node gather --------------------------
__global__ __launch_bounds__(256) void k_agg1(const float* __restrict__ bias) {
    int gw   = (blockIdx.x * blockDim.x + threadIdx.x) >> 5;
    int lane = threadIdx.x & 31;
    if (gw >= N_NODES) return;
    int n  = gw;
    int eg = lane >> 2, c = lane & 3;

    const float4* H = (const float4*)g_h1;
    float4 acc = make_float4(0.f, 0.f, 0.f, 0.f);

    int j0 = g_row[n], je = g_row[n + 1];
    for (int j = j0; j < je; j += 8) {
        int jj = j + eg;
        if (jj < je) {
            float4 v = __ldg(&H[g_edge[jj] * 4 + c]);
            acc.x += v.x; acc.y += v.y; acc.z += v.z; acc.w += v.w;
        }
    }
#pragma unroll
    for (int o = 16; o >= 4; o >>= 1) {
        acc.x += __shfl_xor_sync(0xffffffffu, acc.x, o);
        acc.y += __shfl_xor_sync(0xffffffffu, acc.y, o);
        acc.z += __shfl_xor_sync(0xffffffffu, acc.z, o);
        acc.w += __shfl_xor_sync(0xffffffffu, acc.w, o);
    }

    if (lane < 4) {
        float4 self = __ldg(&H[n * 4 + lane]);
        acc.x += self.x; acc.y += self.y; acc.z += self.z; acc.w += self.w;
        float dn = g_dinv[n];
        float4 b = __ldg((const float4*)bias + lane);
        acc.x = dn * fmaxf(dn * acc.x + b.x, 0.0f);
        acc.y = dn * fmaxf(dn * acc.y + b.y, 0.0f);
        acc.z = dn * fmaxf(dn * acc.z + b.z, 0.0f);
        acc.w = dn * fmaxf(dn * acc.w + b.w, 0.0f);
        ((float4*)g_h2)[n * 4 + lane] = acc;
    }
}

// ---------------- agg layer 2 fused with GEMM2 + log_softmax ----------------
__global__ __launch_bounds__(256) void k_agg2f(const float* __restrict__ W2,
                                               const float* __restrict__ b2,
                                               float* __restrict__ out) {
    __shared__ float W2s[HID * N_CLS];
    __shared__ float b2s[N_CLS];
    for (int i = threadIdx.x; i < HID * N_CLS; i += blockDim.x) W2s[i] = W2[i];
    for (int i = threadIdx.x; i < N_CLS; i += blockDim.x) b2s[i] = b2[i];
    __syncthreads();

    int gw   = (blockIdx.x * blockDim.x + threadIdx.x) >> 5;
    int lane = threadIdx.x & 31;
    if (gw >= N_NODES) return;
    int n  = gw;
    int eg = lane >> 2, c = lane & 3;

    const float4* H = (const float4*)g_h2;
    float4 acc = make_float4(0.f, 0.f, 0.f, 0.f);

    int j0 = g_row[n], je = g_row[n + 1];
    for (int j = j0; j < je; j += 8) {
        int jj = j + eg;
        if (jj < je) {
            float4 v = __ldg(&H[g_edge[jj] * 4 + c]);
            acc.x += v.x; acc.y += v.y; acc.z += v.z; acc.w += v.w;
        }
    }
#pragma unroll
    for (int o = 16; o >= 4; o >>= 1) {
        acc.x += __shfl_xor_sync(0xffffffffu, acc.x, o);
        acc.y += __shfl_xor_sync(0xffffffffu, acc.y, o);
        acc.z += __shfl_xor_sync(0xffffffffu, acc.z, o);
        acc.w += __shfl_xor_sync(0xffffffffu, acc.w, o);
    }
    float4 self = __ldg(&H[n * 4 + c]);
    float dn = g_dinv[n];
    acc.x = dn * (acc.x + self.x);
    acc.y = dn * (acc.y + self.y);
    acc.z = dn * (acc.z + self.z);
    acc.w = dn * (acc.w + self.w);

    float z0 = b2s[lane], z1 = b2s[lane + 32];
#pragma unroll
    for (int j = 0; j < HID; j++) {
        int q = j >> 2, r = j & 3;
        float comp = (r == 0) ? acc.x : (r == 1) ? acc.y : (r == 2) ? acc.z : acc.w;
        float t = __shfl_sync(0xffffffffu, comp, q);
        z0 += t * W2s[j * N_CLS + lane];
        z1 += t * W2s[j * N_CLS + lane + 32];
    }

    float m = fmaxf(z0, z1);
#pragma unroll
    for (int off = 16; off > 0; off >>= 1)
        m = fmaxf(m, __shfl_xor_sync(0xffffffffu, m, off));
    float s = __expf(z0 - m) + __expf(z1 - m);
#pragma unroll
    for (int off = 16; off > 0; off >>= 1)
        s += __shfl_xor_sync(0xffffffffu, s, off);
    float l = m + __logf(s);

    out[n * N_CLS + lane]      = z0 - l;
    out[n * N_CLS + lane + 32] = z1 - l;
}

// ---------------- launch ----------------------------------------------------
extern "C" void kernel_launch(void* const* d_in, const int* in_sizes, int n_in,
                              void* d_out, int out_size) {
    const float* x    = (const float*)d_in[0];
    const void*  eidx = d_in[1];
    const float* W1   = (const float*)d_in[2];
    const float* b1   = (const float*)d_in[3];
    const float* W2   = (const float*)d_in[4];
    const float* b2   = (const float*)d_in[5];
    float* out = (float*)d_out;

    int E = in_sizes[1] / 2;
    if (E > N_EDGES) E = N_EDGES;

    const int T = 256;
    int nb_edges = (E + T - 1) / T;
    int nb_warp  = (N_NODES * 32 + T - 1) / T;
    int nb_gemm  = (N_NODES + 255) / 256;

    cudaFuncSetAttribute(k_gemm1, cudaFuncAttributeMaxDynamicSharedMemorySize,
                         G_SMEM_BYTES);

    k_hist<<<nb_edges, T>>>(eidx, E);
    k_scan<<<NB_N, T>>>();
    k_fill<<<nb_edges, T>>>(eidx, E);
    k_gemm1<<<nb_gemm, T, G_SMEM_BYTES>>>(x, W1);
    k_agg1<<<nb_warp, T>>>(b1);
    k_agg2f<<<nb_warp, T>>>(W2, b2, out);
}

// round 14
// speedup vs baseline: 1.4397x; 1.4397x over previous
#include <cuda_runtime.h>

#define N_NODES 100000
#define N_EDGES 3200000
#define N_FEAT  512
#define HID     16
#define N_CLS   64
#define NB_N    391              // ceil(N_NODES/256)

// ---------------- scratch (device globals; statically zero-initialized) ----
__device__ float g_h1[N_NODES * HID];    // dinv-scaled x@W1
__device__ float g_h2[N_NODES * HID];    // dinv-scaled layer-1 output
__device__ float g_dinv[N_NODES];
__device__ int   g_cnt[N_NODES];         // in-degree histogram (re-zeroed by k_scan)
__device__ int   g_row[N_NODES + 1];     // CSR row offsets
__device__ int   g_cursor[N_NODES];
__device__ int   g_edge[N_EDGES];        // src only, dst-grouped
__device__ unsigned long long g_state[NB_N];  // lookback: status(hi32) | value(lo32)
__device__ int   g_is64;

// ---------------- hist: per-block dtype detect + degree histogram -----------
__global__ __launch_bounds__(256) void k_hist(const void* __restrict__ eidx, int E) {
    int gtid = blockIdx.x * blockDim.x + threadIdx.x;
    if (gtid < NB_N) g_state[gtid] = 0ull;

    unsigned w = 0;
    if (threadIdx.x < 32) {
        int ee = blockIdx.x * blockDim.x + threadIdx.x;
        if (ee < E) w = ((const unsigned*)eidx)[2 * ee + 1];
    }
    int any = __syncthreads_or((int)(w != 0));
    int is64 = (any == 0);
    if (blockIdx.x == 0 && threadIdx.x == 0) g_is64 = is64;

    if (gtid < E) {
        int d = is64 ? (int)((const long long*)eidx)[E + gtid]
                     : ((const int*)eidx)[E + gtid];
        atomicAdd(&g_cnt[d], 1);
    }
}

// ---------------- single-kernel scan (decoupled lookback) -------------------
__global__ __launch_bounds__(256) void k_scan() {
    int i    = blockIdx.x * blockDim.x + threadIdx.x;
    int lane = threadIdx.x & 31, warp = threadIdx.x >> 5;
    int v = (i < N_NODES) ? g_cnt[i] : 0;

    int x = v;
#pragma unroll
    for (int o = 1; o < 32; o <<= 1) {
        int y = __shfl_up_sync(0xffffffffu, x, o);
        if (lane >= o) x += y;
    }
    __shared__ int ws[8];
    __shared__ int s_pref;
    if (lane == 31) ws[warp] = x;
    __syncthreads();

    if (threadIdx.x == 0) {
        int s = 0;
#pragma unroll
        for (int k = 0; k < 8; k++) { int t = ws[k]; ws[k] = s; s += t; }
        int total = s;
        int prefix = 0;
        if (blockIdx.x == 0) {
            __threadfence();
            atomicExch(&g_state[0], (2ull << 32) | (unsigned)total);          // P
        } else {
            atomicExch(&g_state[blockIdx.x], (1ull << 32) | (unsigned)total); // A
            int p = blockIdx.x - 1;
            unsigned ns = 32;
            while (true) {
                unsigned long long st = *(volatile unsigned long long*)&g_state[p];
                unsigned stat = (unsigned)(st >> 32);
                if (stat == 0u) {
                    __nanosleep(ns);
                    if (ns < 1024u) ns <<= 1;
                    continue;
                }
                ns = 32;
                prefix += (int)(unsigned)(st & 0xffffffffu);
                if (stat == 2u) break;
                p--;
            }
            __threadfence();
            atomicExch(&g_state[blockIdx.x],
                       (2ull << 32) | (unsigned)(prefix + total));            // P
        }
        s_pref = prefix;
    }
    __syncthreads();

    int excl = s_pref + ws[warp] + x - v;
    if (i < N_NODES) {
        g_row[i]    = excl;
        g_cursor[i] = excl;
        g_dinv[i]   = rsqrtf((float)v + 1.0f);     // +1: self-loop
        g_cnt[i]    = 0;                            // ready for next replay
        if (i == N_NODES - 1) g_row[N_NODES] = excl + v;
    }
}

// ---------------- fill CSR: dst-grouped src index ---------------------------
__global__ __launch_bounds__(256) void k_fill(const void* __restrict__ eidx, int E) {
    int e = blockIdx.x * blockDim.x + threadIdx.x;
    if (e >= E) return;
    int s, d;
    if (g_is64) {
        const long long* p = (const long long*)eidx;
        s = (int)p[e]; d = (int)p[E + e];
    } else {
        const int* p = (const int*)eidx;
        s = p[e]; d = p[E + e];
    }
    int pos = atomicAdd(&g_cursor[d], 1);
    g_edge[pos] = s;
}

// ---------------- GEMM1 v4: 4 nodes/warp, wide loads, barrier-free loop -----
// lane covers k-pair (k = k0 + 2*lane); 8 chunks of 64 k, fully unrolled.
// x via LDG.64; W pairs via LDS.128 (contiguous 512B/warp = 4 wavefronts).
__global__ __launch_bounds__(256) void k_gemm1(const float* __restrict__ x,
                                               const float* __restrict__ W1) {
    __shared__ float2 Ws2[8 * N_FEAT];   // Ws2[j2*512 + k] = (W1[k][2j2], W1[k][2j2+1])
    for (int idx = threadIdx.x; idx < 8 * N_FEAT; idx += blockDim.x) {
        int j2 = idx & 7, k = idx >> 3;
        Ws2[j2 * N_FEAT + k] = make_float2(W1[k * HID + 2 * j2],
                                           W1[k * HID + 2 * j2 + 1]);
    }
    __syncthreads();

    int lane  = threadIdx.x & 31;
    int warp  = threadIdx.x >> 5;
    int nbase = blockIdx.x * 32 + warp * 4;

    unsigned long long acc[4][8];
#pragma unroll
    for (int c = 0; c < 4; c++)
#pragma unroll
        for (int j = 0; j < 8; j++) acc[c][j] = 0ull;

#pragma unroll
    for (int chunk = 0; chunk < 8; chunk++) {
        int k0 = chunk * 64;
        // x: lane's k-pair for each of 4 nodes (LDG.64, coalesced 256B/warp)
        float2 xv[4];
#pragma unroll
        for (int c = 0; c < 4; c++)
            xv[c] = __ldg((const float2*)(x + (size_t)(nbase + c) * N_FEAT + k0) + lane);
        unsigned long long xk[4], xk1[4];
#pragma unroll
        for (int c = 0; c < 4; c++) {
            asm("mov.b64 %0, {%1, %1};" : "=l"(xk[c])  : "f"(xv[c].x));
            asm("mov.b64 %0, {%1, %1};" : "=l"(xk1[c]) : "f"(xv[c].y));
        }
#pragma unroll
        for (int j2 = 0; j2 < 8; j2++) {
            // W for (k, k+1) x (2j2, 2j2+1): one LDS.128, lanes contiguous
            ulonglong2 w = *(const ulonglong2*)&Ws2[j2 * N_FEAT + k0 + 2 * lane];
#pragma unroll
            for (int c = 0; c < 4; c++) {
                asm("fma.rn.f32x2 %0, %1, %2, %0;" : "+l"(acc[c][j2]) : "l"(xk[c]),  "l"(w.x));
                asm("fma.rn.f32x2 %0, %1, %2, %0;" : "+l"(acc[c][j2]) : "l"(xk1[c]), "l"(w.y));
            }
        }
    }

#pragma unroll
    for (int c = 0; c < 4; c++) {
        float av[16];
#pragma unroll
        for (int j2 = 0; j2 < 8; j2++)
            asm("mov.b64 {%0, %1}, %2;"
                : "=f"(av[2 * j2]), "=f"(av[2 * j2 + 1]) : "l"(acc[c][j2]));
        float res = 0.0f;
#pragma unroll
        for (int j = 0; j < 16; j++) {
            float v = av[j];
            v += __shfl_xor_sync(0xffffffffu, v, 16);
            v += __shfl_xor_sync(0xffffffffu, v, 8);
            v += __shfl_xor_sync(0xffffffffu, v, 4);
            v += __shfl_xor_sync(0xffffffffu, v, 2);
            v += __shfl_xor_sync(0xffffffffu, v, 1);
            if (lane == j) res = v;
        }
        if (lane < 16)
            g_h1[(nbase + c) * HID + lane] = res * g_dinv[nbase + c];
    }
}

// ---------------- agg layer 1: warp-per-node gather --------------------------
__global__ __launch_bounds__(256) void k_agg1(const float* __restrict__ bias) {
    int gw   = (blockIdx.x * blockDim.x + threadIdx.x) >> 5;
    int lane = threadIdx.x & 31;
    if (gw >= N_NODES) return;
    int n  = gw;
    int eg = lane >> 2, c = lane & 3;

    const float4* H = (const float4*)g_h1;
    float4 acc = make_float4(0.f, 0.f, 0.f, 0.f);

    int j0 = g_row[n], je = g_row[n + 1];
    for (int j = j0; j < je; j += 8) {
        int jj = j + eg;
        if (jj < je) {
            float4 v = __ldg(&H[g_edge[jj] * 4 + c]);
            acc.x += v.x; acc.y += v.y; acc.z += v.z; acc.w += v.w;
        }
    }
#pragma unroll
    for (int o = 16; o >= 4; o >>= 1) {
        acc.x += __shfl_xor_sync(0xffffffffu, acc.x, o);
        acc.y += __shfl_xor_sync(0xffffffffu, acc.y, o);
        acc.z += __shfl_xor_sync(0xffffffffu, acc.z, o);
        acc.w += __shfl_xor_sync(0xffffffffu, acc.w, o);
    }

    if (lane < 4) {
        float4 self = __ldg(&H[n * 4 + lane]);
        acc.x += self.x; acc.y += self.y; acc.z += self.z; acc.w += self.w;
        float dn = g_dinv[n];
        float4 b = __ldg((const float4*)bias + lane);
        acc.x = dn * fmaxf(dn * acc.x + b.x, 0.0f);
        acc.y = dn * fmaxf(dn * acc.y + b.y, 0.0f);
        acc.z = dn * fmaxf(dn * acc.z + b.z, 0.0f);
        acc.w = dn * fmaxf(dn * acc.w + b.w, 0.0f);
        ((float4*)g_h2)[n * 4 + lane] = acc;
    }
}

// ---------------- agg layer 2 fused with GEMM2 + log_softmax ----------------
__global__ __launch_bounds__(256) void k_agg2f(const float* __restrict__ W2,
                                               const float* __restrict__ b2,
                                               float* __restrict__ out) {
    __shared__ float W2s[HID * N_CLS];
    __shared__ float b2s[N_CLS];
    for (int i = threadIdx.x; i < HID * N_CLS; i += blockDim.x) W2s[i] = W2[i];
    for (int i = threadIdx.x; i < N_CLS; i += blockDim.x) b2s[i] = b2[i];
    __syncthreads();

    int gw   = (blockIdx.x * blockDim.x + threadIdx.x) >> 5;
    int lane = threadIdx.x & 31;
    if (gw >= N_NODES) return;
    int n  = gw;
    int eg = lane >> 2, c = lane & 3;

    const float4* H = (const float4*)g_h2;
    float4 acc = make_float4(0.f, 0.f, 0.f, 0.f);

    int j0 = g_row[n], je = g_row[n + 1];
    for (int j = j0; j < je; j += 8) {
        int jj = j + eg;
        if (jj < je) {
            float4 v = __ldg(&H[g_edge[jj] * 4 + c]);
            acc.x += v.x; acc.y += v.y; acc.z += v.z; acc.w += v.w;
        }
    }
#pragma unroll
    for (int o = 16; o >= 4; o >>= 1) {
        acc.x += __shfl_xor_sync(0xffffffffu, acc.x, o);
        acc.y += __shfl_xor_sync(0xffffffffu, acc.y, o);
        acc.z += __shfl_xor_sync(0xffffffffu, acc.z, o);
        acc.w += __shfl_xor_sync(0xffffffffu, acc.w, o);
    }
    float4 self = __ldg(&H[n * 4 + c]);
    float dn = g_dinv[n];
    acc.x = dn * (acc.x + self.x);
    acc.y = dn * (acc.y + self.y);
    acc.z = dn * (acc.z + self.z);
    acc.w = dn * (acc.w + self.w);

    float z0 = b2s[lane], z1 = b2s[lane + 32];
#pragma unroll
    for (int j = 0; j < HID; j++) {
        int q = j >> 2, r = j & 3;
        float comp = (r == 0) ? acc.x : (r == 1) ? acc.y : (r == 2) ? acc.z : acc.w;
        float t = __shfl_sync(0xffffffffu, comp, q);
        z0 += t * W2s[j * N_CLS + lane];
        z1 += t * W2s[j * N_CLS + lane + 32];
    }

    float m = fmaxf(z0, z1);
#pragma unroll
    for (int off = 16; off > 0; off >>= 1)
        m = fmaxf(m, __shfl_xor_sync(0xffffffffu, m, off));
    float s = __expf(z0 - m) + __expf(z1 - m);
#pragma unroll
    for (int off = 16; off > 0; off >>= 1)
        s += __shfl_xor_sync(0xffffffffu, s, off);
    float l = m + __logf(s);

    out[n * N_CLS + lane]      = z0 - l;
    out[n * N_CLS + lane + 32] = z1 - l;
}

// ---------------- launch ----------------------------------------------------
extern "C" void kernel_launch(void* const* d_in, const int* in_sizes, int n_in,
                              void* d_out, int out_size) {
    const float* x    = (const float*)d_in[0];
    const void*  eidx = d_in[1];
    const float* W1   = (const float*)d_in[2];
    const float* b1   = (const float*)d_in[3];
    const float* W2   = (const float*)d_in[4];
    const float* b2   = (const float*)d_in[5];
    float* out = (float*)d_out;

    int E = in_sizes[1] / 2;
    if (E > N_EDGES) E = N_EDGES;

    const int T = 256;
    int nb_edges = (E + T - 1) / T;
    int nb_warp  = (N_NODES * 32 + T - 1) / T;

    k_hist<<<nb_edges, T>>>(eidx, E);
    k_scan<<<NB_N, T>>>();
    k_fill<<<nb_edges, T>>>(eidx, E);
    k_gemm1<<<N_NODES / 32, T>>>(x, W1);
    k_agg1<<<nb_warp, T>>>(b1);
    k_agg2f<<<nb_warp, T>>>(W2, b2, out);
}